// round 1
// baseline (speedup 1.0000x reference)
#include <cuda_runtime.h>
#include <cstdint>

// Problem constants
#define B_TOT  2048
#define S_LEN  256
#define DIN    3
#define HID    128
#define D_OUT  6
#define DT_F   0.1f

// Tiling: 14 batch rows per CTA (2 groups x 7 rows), 147 CTAs = one wave on 148 SMs
#define ROWS   14
#define RPG    7
#define NCTA   ((B_TOT + ROWS - 1) / ROWS)   // 147
#define NTHR   256

typedef unsigned long long u64;

// ---- packed f32x2 FMA (SASS FFMA2; 2 MACs/lane/instr on sm_103a) ----
__device__ __forceinline__ u64 fma2(u64 a, u64 b, u64 c) {
    u64 d;
    asm("fma.rn.f32x2 %0, %1, %2, %3;" : "=l"(d) : "l"(a), "l"(b), "l"(c));
    return d;
}
__device__ __forceinline__ u64 pk(float lo, float hi) {
    u64 v;
    asm("mov.b64 %0, {%1, %2};" : "=l"(v) : "f"(lo), "f"(hi));
    return v;
}
__device__ __forceinline__ void upk(u64 v, float& lo, float& hi) {
    asm("mov.b64 {%0, %1}, %2;" : "=f"(lo), "=f"(hi) : "l"(v));
}

// Accurate-enough tanh: ex2.approx (~2^-21 rel) + fast divide; abs err ~1e-6.
// (MUFU.TANH alone is ~6e-4 — too risky against the 1e-3 gate.)
__device__ __forceinline__ float fast_tanh(float x) {
    float ax = fminf(fabsf(x), 15.0f);
    float e  = __expf(2.0f * ax);
    float t  = 1.0f - __fdividef(2.0f, e + 1.0f);
    return copysignf(t, x);
}

// softplus(x) = max(x,0) + log1p(exp(-|x|))  (stable, accurate)
__device__ __forceinline__ float softplus_acc(float x) {
    return fmaxf(x, 0.0f) + log1pf(__expf(-fabsf(x)));
}

extern __shared__ float smem_dyn[];

__global__ void __launch_bounds__(NTHR, 1)
cfc_kernel(const float* __restrict__ x,        // [B, S, 3]
           const float* __restrict__ W_xh,     // [128, 3]
           const float* __restrict__ W_hh,     // [128, 128]
           const float* __restrict__ b_hh,     // [128]
           const float* __restrict__ log_tau,  // [128]
           const float* __restrict__ fc_W,     // [6, 128]
           const float* __restrict__ fc_b,     // [6]
           float* __restrict__ out)            // [B, 6]
{
    // Shared layout: x tile then double-buffered h
    float* xsh  = smem_dyn;                       // ROWS * S_LEN * DIN = 10752 floats
    float* hbuf = xsh + ROWS * S_LEN * DIN;       // 2 * ROWS * HID   =  3584 floats

    const int tid = threadIdx.x;
    const int t   = tid & 127;          // neuron owned by this thread
    const int grp = tid >> 7;           // 0 or 1
    const int cb  = blockIdx.x * ROWS;  // global batch-row base of this CTA

    // ---- W_hh row t -> registers, packed as 64 f32x2 pairs (128 regs) ----
    u64 Wp[HID / 2];
    {
        const ulonglong2* wr = reinterpret_cast<const ulonglong2*>(W_hh + t * HID);
        #pragma unroll
        for (int j4 = 0; j4 < HID / 4; j4++) {
            ulonglong2 v = wr[j4];           // 16B load = 2 packed pairs, no MOVs
            Wp[2 * j4]     = v.x;
            Wp[2 * j4 + 1] = v.y;
        }
    }

    // ---- per-neuron scalars ----
    const float wx0 = W_xh[t * 3 + 0];
    const float wx1 = W_xh[t * 3 + 1];
    const float wx2 = W_xh[t * 3 + 2];
    const float bb  = b_hh[t];
    const float tau = softplus_acc(log_tau[t]) + 0.001f;
    const float aa  = DT_F / tau;        // one-time accurate divide

    // ---- stage this CTA's x tile into SMEM (rows are contiguous in gmem) ----
    {
        const int   n   = ROWS * S_LEN * DIN;            // 10752 floats
        const float* src = x + (size_t)cb * (S_LEN * DIN);
        int lim = (B_TOT - cb) * (S_LEN * DIN);          // last CTA is partial
        if (lim > n) lim = n;
        for (int i = tid; i < n; i += NTHR)
            xsh[i] = (i < lim) ? src[i] : 0.0f;
    }
    // zero both h buffers
    for (int i = tid; i < 2 * ROWS * HID; i += NTHR) hbuf[i] = 0.0f;
    __syncthreads();

    const int rb = grp * RPG;           // local row base for this group
    float* h0 = hbuf;
    float* h1 = hbuf + ROWS * HID;

    // ================= sequential scan over S =================
    for (int s = 0; s < S_LEN; s++) {
        const float* hc = (s & 1) ? h1 : h0;   // read buffer
        float*       hn = (s & 1) ? h0 : h1;   // write buffer

        // z init: input projection + bias (x reads are warp-uniform -> broadcast)
        u64 acc[RPG];
        const float* xs = xsh + s * 3;
        #pragma unroll
        for (int r = 0; r < RPG; r++) {
            const float* xr = xs + (rb + r) * (S_LEN * DIN);
            float z = fmaf(wx0, xr[0], fmaf(wx1, xr[1], fmaf(wx2, xr[2], bb)));
            acc[r] = pk(z, 0.0f);
        }

        // matvec: acc[r] += W_row(t) . h[r]  — packed pairs, broadcast LDS.128
        const ulonglong2* hc2 = reinterpret_cast<const ulonglong2*>(hc + rb * HID);
        #pragma unroll
        for (int j4 = 0; j4 < HID / 4; j4++) {
            #pragma unroll
            for (int r = 0; r < RPG; r++) {
                ulonglong2 hv = hc2[r * (HID / 4) + j4];  // same addr all lanes
                acc[r] = fma2(Wp[2 * j4],     hv.x, acc[r]);
                acc[r] = fma2(Wp[2 * j4 + 1], hv.y, acc[r]);
            }
        }

        // activation + leaky update
        #pragma unroll
        for (int r = 0; r < RPG; r++) {
            float lo, hi;
            upk(acc[r], lo, hi);
            float f    = fast_tanh(lo + hi);
            float hold = hc[(rb + r) * HID + t];            // stride-1, no conflicts
            hn[(rb + r) * HID + t] = fmaf(aa, f - hold, hold);
        }
        __syncthreads();
    }

    // ================= output head: softplus(h_T @ fc_W^T + fc_b) =================
    const float* hf = h0;   // after 256 steps, final state is in buffer 0
    if (tid < ROWS * D_OUT) {
        const int r = tid / D_OUT;
        const int o = tid % D_OUT;
        const int grow = cb + r;
        if (grow < B_TOT) {
            const float4* w4 = reinterpret_cast<const float4*>(fc_W + o * HID);
            const float4* h4 = reinterpret_cast<const float4*>(hf + r * HID);
            float z = fc_b[o];
            #pragma unroll
            for (int j = 0; j < HID / 4; j++) {
                float4 w = w4[j];
                float4 h = h4[j];
                z = fmaf(w.x, h.x, fmaf(w.y, h.y, fmaf(w.z, h.z, fmaf(w.w, h.w, z))));
            }
            out[grow * D_OUT + o] = softplus_acc(z);
        }
    }
}

extern "C" void kernel_launch(void* const* d_in, const int* in_sizes, int n_in,
                              void* d_out, int out_size) {
    const float* x       = (const float*)d_in[0];
    const float* W_xh    = (const float*)d_in[1];
    const float* W_hh    = (const float*)d_in[2];
    const float* b_hh    = (const float*)d_in[3];
    const float* log_tau = (const float*)d_in[4];
    const float* fc_W    = (const float*)d_in[5];
    const float* fc_b    = (const float*)d_in[6];
    float* out = (float*)d_out;

    const size_t shmem = (size_t)(ROWS * S_LEN * DIN + 2 * ROWS * HID) * sizeof(float); // 57344 B
    cudaFuncSetAttribute(cfc_kernel, cudaFuncAttributeMaxDynamicSharedMemorySize, (int)shmem);

    cfc_kernel<<<NCTA, NTHR, shmem>>>(x, W_xh, W_hh, b_hh, log_tau, fc_W, fc_b, out);
}

// round 2
// speedup vs baseline: 1.0034x; 1.0034x over previous
#include <cuda_runtime.h>
#include <cstdint>

// Problem constants
#define B_TOT  2048
#define S_LEN  256
#define DIN    3
#define HID    128
#define D_OUT  6
#define DT_F   0.1f

// Tiling: 14 batch rows per CTA (2 groups x 7 rows), 147 CTAs (one wave on 148 SMs)
// Thread layout (256 threads): tp = tid&63 (neuron PAIR), kh = (tid>>6)&1 (k-half),
// g = tid>>7 (row group). Warps are uniform in (kh, g) -> all h loads broadcast.
#define ROWS   14
#define RPG    7
#define NCTA   ((B_TOT + ROWS - 1) / ROWS)   // 147
#define NTHR   256

typedef unsigned long long u64;

// ---- packed f32x2 FMA (SASS FFMA2; 2 MACs/lane/instr on sm_103a) ----
__device__ __forceinline__ u64 fma2(u64 a, u64 b, u64 c) {
    u64 d;
    asm("fma.rn.f32x2 %0, %1, %2, %3;" : "=l"(d) : "l"(a), "l"(b), "l"(c));
    return d;
}
__device__ __forceinline__ u64 pk(float lo, float hi) {
    u64 v;
    asm("mov.b64 %0, {%1, %2};" : "=l"(v) : "f"(lo), "f"(hi));
    return v;
}
__device__ __forceinline__ void upk(u64 v, float& lo, float& hi) {
    asm("mov.b64 {%0, %1}, %2;" : "=f"(lo), "=f"(hi) : "l"(v));
}

// Accurate-enough tanh: ex2.approx + fast divide; abs err ~1e-6.
__device__ __forceinline__ float fast_tanh(float x) {
    float ax = fminf(fabsf(x), 15.0f);
    float e  = __expf(2.0f * ax);
    float t  = 1.0f - __fdividef(2.0f, e + 1.0f);
    return copysignf(t, x);
}

// softplus(x) = max(x,0) + log1p(exp(-|x|))  (stable, accurate)
__device__ __forceinline__ float softplus_acc(float x) {
    return fmaxf(x, 0.0f) + log1pf(__expf(-fabsf(x)));
}

extern __shared__ float smem_dyn[];

__global__ void __launch_bounds__(NTHR, 1)
cfc_kernel(const float* __restrict__ x,        // [B, S, 3]
           const float* __restrict__ W_xh,     // [128, 3]
           const float* __restrict__ W_hh,     // [128, 128]
           const float* __restrict__ b_hh,     // [128]
           const float* __restrict__ log_tau,  // [128]
           const float* __restrict__ fc_W,     // [6, 128]
           const float* __restrict__ fc_b,     // [6]
           float* __restrict__ out)            // [B, 6]
{
    // Shared layout: x tile | double-buffered h | k-split partial buffer
    float* xsh  = smem_dyn;                       // ROWS*S_LEN*DIN = 10752 floats
    float* hbuf = xsh + ROWS * S_LEN * DIN;       // 2*ROWS*HID    =  3584 floats
    float* part = hbuf + 2 * ROWS * HID;          // 2(kh)*2(g)*RPG*HID = 3584 floats

    const int tid = threadIdx.x;
    const int tp  = tid & 63;            // neuron pair index: owns t0=2tp, t1=2tp+1
    const int kh  = (tid >> 6) & 1;      // k-half: j in [kh*64, kh*64+64)
    const int g   = tid >> 7;            // row group (0 or 1)
    const int t0  = 2 * tp;
    const int t1  = 2 * tp + 1;
    const int cb  = blockIdx.x * ROWS;   // global batch-row base

    // ---- W_hh rows t0,t1 (this thread's j-half) -> registers as f32x2 pairs ----
    u64 W0[32], W1[32];                  // 2 x 32 u64 = 128 x 32-bit regs
    {
        const ulonglong2* w0 = reinterpret_cast<const ulonglong2*>(W_hh + t0 * HID + kh * 64);
        const ulonglong2* w1 = reinterpret_cast<const ulonglong2*>(W_hh + t1 * HID + kh * 64);
        #pragma unroll
        for (int j4 = 0; j4 < 16; j4++) {
            ulonglong2 a = w0[j4];
            W0[2 * j4] = a.x; W0[2 * j4 + 1] = a.y;
            ulonglong2 b = w1[j4];
            W1[2 * j4] = b.x; W1[2 * j4 + 1] = b.y;
        }
    }

    // ---- per-neuron scalars (both neurons) ----
    const float wx00 = W_xh[t0 * 3 + 0], wx01 = W_xh[t0 * 3 + 1], wx02 = W_xh[t0 * 3 + 2];
    const float wx10 = W_xh[t1 * 3 + 0], wx11 = W_xh[t1 * 3 + 1], wx12 = W_xh[t1 * 3 + 2];
    const float bb0 = b_hh[t0], bb1 = b_hh[t1];
    const float aa0 = DT_F / (softplus_acc(log_tau[t0]) + 0.001f);
    const float aa1 = DT_F / (softplus_acc(log_tau[t1]) + 0.001f);

    // ---- stage x tile into SMEM ----
    {
        const int n = ROWS * S_LEN * DIN;
        const float* src = x + (size_t)cb * (S_LEN * DIN);
        int lim = (B_TOT - cb) * (S_LEN * DIN);
        if (lim > n) lim = n;
        for (int i = tid; i < n; i += NTHR)
            xsh[i] = (i < lim) ? src[i] : 0.0f;
    }
    for (int i = tid; i < 2 * ROWS * HID; i += NTHR) hbuf[i] = 0.0f;
    __syncthreads();

    const int rb = g * RPG;                 // local row base for this group
    float* h0 = hbuf;
    float* h1 = hbuf + ROWS * HID;

    // Finish-phase row assignment: kh=0 handles rows [0,4), kh=1 rows [4,7) of its group
    const int r_lo = kh ? 4 : 0;
    const int r_hi = kh ? RPG : 4;

    // partial buffer slots: part[kh][g][r][t], stored/loaded as u64 pairs at t0
    float* my_part    = part + ((kh * 2 + g) * RPG) * HID;
    float* other_part = part + (((kh ^ 1) * 2 + g) * RPG) * HID;

    // ================= sequential scan over S =================
    for (int s = 0; s < S_LEN; s++) {
        const float* hc = (s & 1) ? h1 : h0;   // read buffer
        float*       hn = (s & 1) ? h0 : h1;   // write buffer

        // matvec partials over this thread's j-half, 2 neurons x RPG rows
        u64 acc0[RPG], acc1[RPG];
        #pragma unroll
        for (int r = 0; r < RPG; r++) { acc0[r] = 0ull; acc1[r] = 0ull; }

        #pragma unroll
        for (int j4 = 0; j4 < 16; j4++) {
            #pragma unroll
            for (int r = 0; r < RPG; r++) {
                // warp-uniform broadcast: 4 h-floats feed 4 FFMA2 (8 MACs)
                ulonglong2 hv = *reinterpret_cast<const ulonglong2*>(
                    hc + (rb + r) * HID + kh * 64 + j4 * 4);
                acc0[r] = fma2(W0[2 * j4],     hv.x, acc0[r]);
                acc0[r] = fma2(W0[2 * j4 + 1], hv.y, acc0[r]);
                acc1[r] = fma2(W1[2 * j4],     hv.x, acc1[r]);
                acc1[r] = fma2(W1[2 * j4 + 1], hv.y, acc1[r]);
            }
        }

        // horizontal-sum partials and publish to SMEM (u64 per row: (z_t0, z_t1))
        #pragma unroll
        for (int r = 0; r < RPG; r++) {
            float a, b, c, d;
            upk(acc0[r], a, b);
            upk(acc1[r], c, d);
            *reinterpret_cast<u64*>(my_part + r * HID + t0) = pk(a + b, c + d);
        }
        __syncthreads();

        // finish assigned rows: combine halves, + x-proj + bias, tanh, leaky update
        for (int r = r_lo; r < r_hi; r++) {
            u64 pv = *reinterpret_cast<const u64*>(other_part + r * HID + t0);
            float q0, q1;
            upk(pv, q0, q1);
            float a, b, c, d;
            upk(acc0[r], a, b);
            upk(acc1[r], c, d);
            const float* xr = xsh + (rb + r) * (S_LEN * DIN) + s * 3;
            float x0 = xr[0], x1 = xr[1], x2 = xr[2];
            float z0 = (a + b) + q0 + fmaf(wx00, x0, fmaf(wx01, x1, fmaf(wx02, x2, bb0)));
            float z1 = (c + d) + q1 + fmaf(wx10, x0, fmaf(wx11, x1, fmaf(wx12, x2, bb1)));
            float f0 = fast_tanh(z0);
            float f1 = fast_tanh(z1);
            u64 hov = *reinterpret_cast<const u64*>(hc + (rb + r) * HID + t0);
            float ho0, ho1;
            upk(hov, ho0, ho1);
            float hn0 = fmaf(aa0, f0 - ho0, ho0);
            float hn1 = fmaf(aa1, f1 - ho1, ho1);
            *reinterpret_cast<u64*>(hn + (rb + r) * HID + t0) = pk(hn0, hn1);
        }
        __syncthreads();
    }

    // ================= output head: softplus(h_T @ fc_W^T + fc_b) =================
    const float* hf = h0;   // S_LEN even -> final state in buffer 0
    if (tid < ROWS * D_OUT) {
        const int r = tid / D_OUT;
        const int o = tid % D_OUT;
        const int grow = cb + r;
        if (grow < B_TOT) {
            const float4* w4 = reinterpret_cast<const float4*>(fc_W + o * HID);
            const float4* h4 = reinterpret_cast<const float4*>(hf + r * HID);
            float z = fc_b[o];
            #pragma unroll
            for (int j = 0; j < HID / 4; j++) {
                float4 w = w4[j];
                float4 h = h4[j];
                z = fmaf(w.x, h.x, fmaf(w.y, h.y, fmaf(w.z, h.z, fmaf(w.w, h.w, z))));
            }
            out[grow * D_OUT + o] = softplus_acc(z);
        }
    }
}

extern "C" void kernel_launch(void* const* d_in, const int* in_sizes, int n_in,
                              void* d_out, int out_size) {
    const float* x       = (const float*)d_in[0];
    const float* W_xh    = (const float*)d_in[1];
    const float* W_hh    = (const float*)d_in[2];
    const float* b_hh    = (const float*)d_in[3];
    const float* log_tau = (const float*)d_in[4];
    const float* fc_W    = (const float*)d_in[5];
    const float* fc_b    = (const float*)d_in[6];
    float* out = (float*)d_out;

    const size_t shmem = (size_t)(ROWS * S_LEN * DIN + 2 * ROWS * HID
                                  + 2 * 2 * RPG * HID) * sizeof(float);  // 71680 B
    cudaFuncSetAttribute(cfc_kernel, cudaFuncAttributeMaxDynamicSharedMemorySize, (int)shmem);

    cfc_kernel<<<NCTA, NTHR, shmem>>>(x, W_xh, W_hh, b_hh, log_tau, fc_W, fc_b, out);
}